// round 7
// baseline (speedup 1.0000x reference)
#include <cuda_runtime.h>
#include <math.h>
#include <stdint.h>

#define T_STEPS 512
#define BATCH   1024
#define HID     64
#define B_TILE  8
#define NT      512

__device__ float g_buf0[BATCH * T_STEPS * HID];   // layer0 -> layer1
__device__ float g_buf1[BATCH * T_STEPS * HID];   // layer1 -> layer2

__device__ __forceinline__ float sigf(float x) {
    return __fdividef(1.0f, 1.0f + __expf(-x));
}
__device__ __forceinline__ float tanh_fast(float x) {
    float t = fabsf(x);
    float e = __expf(-2.0f * t);
    float r = __fdividef(1.0f - e, 1.0f + e);
    return copysignf(r, x);
}
__device__ __forceinline__ uint64_t pack2(float lo, float hi) {
    uint64_t r; asm("mov.b64 %0, {%1, %2};" : "=l"(r) : "f"(lo), "f"(hi)); return r;
}
__device__ __forceinline__ void unpack2(uint64_t v, float& lo, float& hi) {
    asm("mov.b64 {%0, %1}, %2;" : "=f"(lo), "=f"(hi) : "l"(v));
}
// d += a * b, two packed fp32 lanes (Blackwell FFMA2)
__device__ __forceinline__ void ffma2(uint64_t& d, uint64_t a, uint64_t b) {
    asm("fma.rn.f32x2 %0, %1, %2, %0;" : "+l"(d) : "l"(a), "l"(b));
}
__device__ __forceinline__ float hsum(uint64_t v) {
    float lo, hi; unpack2(v, lo, hi); return lo + hi;
}

// One CTA = 8 batch elements, 512 threads (16 warps).
// GEMM: thread = (unit u = tid&63, K-eighth ke = tid>>6).
//   Computes ALL 4 gate columns of unit u over its K/8 reduction range,
//   batches in two passes of 4 (keeps acc at 16 u64). Per k2 per pass:
//   2 broadcast LDS.128 feed 16 ffma2. Weights (4 x K2T u64) in registers.
// Staging: gs[b][ke][u] = float4(i,f,g,o partial sums) - STS.128 conflict-free.
// Epilogue: thread = (u = tid&63, b_e = tid>>6): sum 8 eighths + bias,
//   activations, c/h update.
template <int IN_W, bool LAST>
__global__ void __launch_bounds__(NT, 1)
lstm_layer(const float* __restrict__ x,     // [B][T][IN_W]
           const float* __restrict__ w_ih,  // [256][IN_W]
           const float* __restrict__ w_hh,  // [256][64]
           const float* __restrict__ b_ih,
           const float* __restrict__ b_hh,
           float* __restrict__ y,           // [B][T][64], or out[B][2] if LAST
           const float* __restrict__ fc1_w, const float* __restrict__ fc1_b,
           const float* __restrict__ fc3_w, const float* __restrict__ fc3_b,
           const float* __restrict__ fc2_w, const float* __restrict__ fc2_b)
{
    constexpr int K   = IN_W + HID;
    constexpr int K2  = K / 2;             // packed k-pairs (35 or 64)
    constexpr int K2T = (K2 + 7) / 8;      // per-thread k2 count (5 or 8)
    constexpr int K2P = 8 * K2T;           // padded k2 rows (40 or 64)
    constexpr int R64 = 10;                // u64 per xh row (8 data + 2 pad)

    extern __shared__ uint64_t smem[];
    uint64_t* xh   = smem;                          // [K2P][R64]
    float4*   gs   = (float4*)(xh + K2P * R64);     // [8b][8ke][64u] = 64KB
    float*    head = (float*)(gs + 8 * 8 * 64);     // LAST only

    const int tid = threadIdx.x;
    const int b0  = blockIdx.x * B_TILE;

    // ---- role identity (GEMM and epilogue use the same split) ----
    const int u  = tid & 63;               // unit
    const int ke = tid >> 6;               // K-eighth (GEMM) / batch (epilogue)
    const int b_e = ke;

    // ---- weights -> registers (one time): 4 gate rows of unit u ----
    uint64_t w[4][K2T];
#pragma unroll
    for (int gt = 0; gt < 4; gt++) {
        const int r = gt * HID + u;        // gate-major row
#pragma unroll
        for (int i = 0; i < K2T; i++) {
            int k2g = ke * K2T + i;
            float w0 = 0.f, w1 = 0.f;
            if (k2g < K2) {
                int k = 2 * k2g;
                if (k < IN_W) { w0 = w_ih[r * IN_W + k];         w1 = w_ih[r * IN_W + k + 1]; }
                else          { int kk = k - IN_W;
                                w0 = w_hh[r * HID + kk];         w1 = w_hh[r * HID + kk + 1]; }
            }
            w[gt][i] = pack2(w0, w1);
        }
    }

    // ---- epilogue bias ----
    float4 bias;
    bias.x = b_ih[0 * HID + u] + b_hh[0 * HID + u];
    bias.y = b_ih[1 * HID + u] + b_hh[1 * HID + u];
    bias.z = b_ih[2 * HID + u] + b_hh[2 * HID + u];
    bias.w = b_ih[3 * HID + u] + b_hh[3 * HID + u];

    // ---- init: zero xh (incl. pad rows), then x(0) ----
    for (int i = tid; i < K2P * R64; i += NT) xh[i] = 0ull;
    __syncthreads();
    if (IN_W == 64) {
        if (tid < 256) {
            int b = tid >> 5, l = tid & 31;
            float2 v = *(const float2*)(x + ((size_t)(b0 + b) * T_STEPS + 0) * IN_W + 2 * l);
            xh[l * R64 + b] = pack2(v.x, v.y);
        }
    } else {
        if (tid < (IN_W / 2) * 8) {
            int k2 = tid >> 3, b = tid & 7;
            float2 v = *(const float2*)(x + ((size_t)(b0 + b) * T_STEPS + 0) * IN_W + 2 * k2);
            xh[k2 * R64 + b] = pack2(v.x, v.y);
        }
    }
    __syncthreads();

    const ulonglong2* XH2 =
        (const ulonglong2*)(xh + (size_t)ke * K2T * R64);   // this eighth's rows
    float c_state = 0.0f;

    for (int t = 0; t < T_STEPS; t++) {
        // prefetch x(t+1) (hidden under the k-loop)
        float2 xpre = make_float2(0.f, 0.f);
        if (t + 1 < T_STEPS) {
            if (IN_W == 64) {
                if (tid < 256) {
                    int b = tid >> 5, l = tid & 31;
                    xpre = *(const float2*)(x + ((size_t)(b0 + b) * T_STEPS + (t + 1)) * IN_W + 2 * l);
                }
            } else if (tid < (IN_W / 2) * 8) {
                int k2 = tid >> 3, b = tid & 7;
                xpre = *(const float2*)(x + ((size_t)(b0 + b) * T_STEPS + (t + 1)) * IN_W + 2 * k2);
            }
        }

        // ---- gate GEMM: 4 columns, this K-eighth, 2 passes of 4 batches ----
#pragma unroll
        for (int p = 0; p < 2; p++) {
            uint64_t acc[4][4];            // [gate][batch-in-pass]
#pragma unroll
            for (int gt = 0; gt < 4; gt++)
#pragma unroll
                for (int j = 0; j < 4; j++) acc[gt][j] = 0ull;
#pragma unroll
            for (int i = 0; i < K2T; i++) {
                ulonglong2 a0 = XH2[i * (R64 / 2) + 2 * p + 0];  // batches 4p,4p+1
                ulonglong2 a1 = XH2[i * (R64 / 2) + 2 * p + 1];  // batches 4p+2,4p+3
                uint64_t w0 = w[0][i], w1 = w[1][i], w2 = w[2][i], w3 = w[3][i];
                ffma2(acc[0][0], a0.x, w0); ffma2(acc[1][0], a0.x, w1);
                ffma2(acc[2][0], a0.x, w2); ffma2(acc[3][0], a0.x, w3);
                ffma2(acc[0][1], a0.y, w0); ffma2(acc[1][1], a0.y, w1);
                ffma2(acc[2][1], a0.y, w2); ffma2(acc[3][1], a0.y, w3);
                ffma2(acc[0][2], a1.x, w0); ffma2(acc[1][2], a1.x, w1);
                ffma2(acc[2][2], a1.x, w2); ffma2(acc[3][2], a1.x, w3);
                ffma2(acc[0][3], a1.y, w0); ffma2(acc[1][3], a1.y, w1);
                ffma2(acc[2][3], a1.y, w2); ffma2(acc[3][3], a1.y, w3);
            }
            // stage: gs[b][ke][u] = (i,f,g,o) partial sums
#pragma unroll
            for (int j = 0; j < 4; j++) {
                float4 v;
                v.x = hsum(acc[0][j]);
                v.y = hsum(acc[1][j]);
                v.z = hsum(acc[2][j]);
                v.w = hsum(acc[3][j]);
                gs[((4 * p + j) * 8 + ke) * 64 + u] = v;
            }
        }
        __syncthreads();   // gates staged; all xh reads for step t done

        // ---- epilogue for (u, b_e) ----
        {
            float4 q = gs[(b_e * 8 + 0) * 64 + u];
            float gi = q.x, gf = q.y, gg = q.z, go = q.w;
#pragma unroll
            for (int kk = 1; kk < 8; kk++) {
                float4 r = gs[(b_e * 8 + kk) * 64 + u];
                gi += r.x; gf += r.y; gg += r.z; go += r.w;
            }
            gi += bias.x; gf += bias.y; gg += bias.z; go += bias.w;
            float iv = sigf(gi), fv = sigf(gf), gv = tanh_fast(gg), ov = sigf(go);
            c_state = fv * c_state + iv * gv;
            float h = ov * tanh_fast(c_state);

            // write h into xh at k = IN_W + u
            float* xf = (float*)xh;
            int k = IN_W + u;
            xf[(k >> 1) * (R64 * 2) + b_e * 2 + (k & 1)] = h;

            if (!LAST) {
                y[((size_t)(b0 + b_e) * T_STEPS + t) * HID + u] = h;
            } else if (t == T_STEPS - 1) {
                head[b_e * HID + u] = h;
            }
        }
        // store prefetched x(t+1)
        if (t + 1 < T_STEPS) {
            if (IN_W == 64) {
                if (tid < 256) {
                    int b = tid >> 5, l = tid & 31;
                    xh[l * R64 + b] = pack2(xpre.x, xpre.y);
                }
            } else if (tid < (IN_W / 2) * 8) {
                int k2 = tid >> 3, b = tid & 7;
                xh[k2 * R64 + b] = pack2(xpre.x, xpre.y);
            }
        }
        __syncthreads();   // xh(t+1) ready
    }

    // ---- fused MLP head (LAST layer only) ----
    if (LAST) {
        float* h_s = head;            // 512 floats  [8][64]
        float* z1  = head + 512;      // 1024        [8][128]
        float* z2  = head + 1536;     // 512         [8][64]
        float* wf1 = head + 2048;     // 8192        fc1_w staged
        float* wf3 = head + 10240;    // 8192        fc3_w staged
        for (int i = tid; i < 128 * 64; i += NT) wf1[i] = fc1_w[i];
        for (int i = tid; i < 64 * 128; i += NT) wf3[i] = fc3_w[i];
        __syncthreads();
        for (int v = tid; v < 8 * 128; v += NT) {
            int b = v >> 7, j = v & 127;
            float s = fc1_b[j];
#pragma unroll 8
            for (int k = 0; k < 64; k++) s += h_s[b * 64 + k] * wf1[j * 64 + k];
            z1[b * 128 + j] = fmaxf(s, 0.0f);
        }
        __syncthreads();
        for (int v = tid; v < 8 * 64; v += NT) {
            int b = v >> 6, j = v & 63;
            float s = fc3_b[j];
#pragma unroll 8
            for (int k = 0; k < 128; k++) s += z1[b * 128 + k] * wf3[j * 128 + k];
            z2[b * 64 + j] = fmaxf(s, 0.0f);
        }
        __syncthreads();
        if (tid < 16) {
            int b = tid >> 1, j = tid & 1;
            float s = fc2_b[j];
#pragma unroll
            for (int k = 0; k < 64; k++) s += z2[b * 64 + k] * fc2_w[j * 64 + k];
            y[(b0 + b) * 2 + j] = s;
        }
    }
}

extern "C" void kernel_launch(void* const* d_in, const int* in_sizes, int n_in,
                              void* d_out, int out_size)
{
    const float* x     = (const float*)d_in[0];
    const float* w_ih0 = (const float*)d_in[1];
    const float* w_hh0 = (const float*)d_in[2];
    const float* b_ih0 = (const float*)d_in[3];
    const float* b_hh0 = (const float*)d_in[4];
    const float* w_ih1 = (const float*)d_in[5];
    const float* w_hh1 = (const float*)d_in[6];
    const float* b_ih1 = (const float*)d_in[7];
    const float* b_hh1 = (const float*)d_in[8];
    const float* w_ih2 = (const float*)d_in[9];
    const float* w_hh2 = (const float*)d_in[10];
    const float* b_ih2 = (const float*)d_in[11];
    const float* b_hh2 = (const float*)d_in[12];
    const float* fc1_w = (const float*)d_in[13];
    const float* fc1_b = (const float*)d_in[14];
    const float* fc3_w = (const float*)d_in[15];
    const float* fc3_b = (const float*)d_in[16];
    const float* fc2_w = (const float*)d_in[17];
    const float* fc2_b = (const float*)d_in[18];
    float* out = (float*)d_out;

    float *buf0 = nullptr, *buf1 = nullptr;
    cudaGetSymbolAddress((void**)&buf0, g_buf0);
    cudaGetSymbolAddress((void**)&buf1, g_buf1);

    // smem: xh (K2P*10 u64) + gs (4096 float4 = 65536B) [+ head for LAST]
    const int SM_L0 = 40 * 10 * 8 + 65536;               // 68736
    const int SM_L1 = 64 * 10 * 8 + 65536;               // 70656
    const int SM_L2 = SM_L1 + 18432 * 4;                 // 144384

    cudaFuncSetAttribute((const void*)lstm_layer<6,  false>,
                         cudaFuncAttributeMaxDynamicSharedMemorySize, SM_L0);
    cudaFuncSetAttribute((const void*)lstm_layer<64, false>,
                         cudaFuncAttributeMaxDynamicSharedMemorySize, SM_L1);
    cudaFuncSetAttribute((const void*)lstm_layer<64, true>,
                         cudaFuncAttributeMaxDynamicSharedMemorySize, SM_L2);

    const int GRID = BATCH / B_TILE;   // 128

    lstm_layer<6,  false><<<GRID, NT, SM_L0>>>(x,    w_ih0, w_hh0, b_ih0, b_hh0, buf0,
                                               nullptr, nullptr, nullptr, nullptr, nullptr, nullptr);
    lstm_layer<64, false><<<GRID, NT, SM_L1>>>(buf0, w_ih1, w_hh1, b_ih1, b_hh1, buf1,
                                               nullptr, nullptr, nullptr, nullptr, nullptr, nullptr);
    lstm_layer<64, true ><<<GRID, NT, SM_L2>>>(buf1, w_ih2, w_hh2, b_ih2, b_hh2, out,
                                               fc1_w, fc1_b, fc3_w, fc3_b, fc2_w, fc2_b);
}

// round 9
// speedup vs baseline: 2.0704x; 2.0704x over previous
#include <cuda_runtime.h>
#include <cuda_bf16.h>
#include <math.h>
#include <stdint.h>

#define T_STEPS 512
#define BATCH   1024
#define HID     64
#define B_TILE  8
#define NT      512

__device__ float g_buf0[BATCH * T_STEPS * HID];   // layer0 -> layer1
__device__ float g_buf1[BATCH * T_STEPS * HID];   // layer1 -> layer2

// ---- smem byte offsets ----
#define XH_STRIDE 272                     // bytes per batch row (136 bf16): conflict-free B-frag loads
#define OFF_BHI   0                       // xh hi: 8 rows x 272B = 2176
#define OFF_BLO   2176                    // xh lo: 2176
#define OFF_GS    4352                    // gate staging: 8 batches x 260 floats = 8320B
#define GS_STRIDE 260
#define OFF_HEAD  12672                   // 2048 floats (LAST only)
#define SM_TOTAL  20864

__device__ __forceinline__ float sigf(float x) {
    return __fdividef(1.0f, 1.0f + __expf(-x));
}
__device__ __forceinline__ float tanh_fast(float x) {
    float t = fabsf(x);
    float e = __expf(-2.0f * t);
    float r = __fdividef(1.0f - e, 1.0f + e);
    return copysignf(r, x);
}
__device__ __forceinline__ uint32_t packbf(float v0, float v1) {
    __nv_bfloat162 h = __floats2bfloat162_rn(v0, v1);
    return *(uint32_t*)&h;
}
// D += A(16x16) * B(16x8), bf16 inputs, f32 accum (sm_80+; valid on sm_100 base)
__device__ __forceinline__ void mma16816(float* d, const uint32_t* a, uint32_t b0, uint32_t b1) {
    asm volatile("mma.sync.aligned.m16n8k16.row.col.f32.bf16.bf16.f32 "
                 "{%0,%1,%2,%3}, {%4,%5,%6,%7}, {%8,%9}, {%0,%1,%2,%3};"
                 : "+f"(d[0]), "+f"(d[1]), "+f"(d[2]), "+f"(d[3])
                 : "r"(a[0]), "r"(a[1]), "r"(a[2]), "r"(a[3]), "r"(b0), "r"(b1));
}

// store one xh value as bf16 hi/lo pair
__device__ __forceinline__ void store_bpair(char* smem, int b, int k, float v) {
    __nv_bfloat16 hi = __float2bfloat16(v);
    __nv_bfloat16 lo = __float2bfloat16(v - __bfloat162float(hi));
    *(__nv_bfloat16*)(smem + OFF_BHI + b * XH_STRIDE + k * 2) = hi;
    *(__nv_bfloat16*)(smem + OFF_BLO + b * XH_STRIDE + k * 2) = lo;
}

// One CTA = 8 batch elements, 512 threads (16 warps).
// GEMM: gates[256,8] = W[256,K] @ xh[8,K]^T via mma.sync m16n8k16 bf16,
//   bf16x3 split (hi*hi + hi*lo + lo*hi) for fp32-grade precision.
//   Warp w owns gate rows 16w..16w+15; A-fragments (weights) persistent in regs.
// Staging: gs[batch][row] floats (stride 260) - conflict-free STS.32.
// Epilogue: thread = (u = tid&63, b = tid>>6): one LDS.128 -> 4 gates,
//   activations, c/h update, h + x(t+1) back into xh bf16 pairs.
template <int IN_W, bool LAST>
__global__ void __launch_bounds__(NT, 1)
lstm_mma(const float* __restrict__ x,     // [B][T][IN_W]
         const float* __restrict__ w_ih,  // [256][IN_W] gate-major rows
         const float* __restrict__ w_hh,  // [256][64]
         const float* __restrict__ b_ih,
         const float* __restrict__ b_hh,
         float* __restrict__ y,           // [B][T][64], or out[B][2] if LAST
         const float* __restrict__ fc1_w, const float* __restrict__ fc1_b,
         const float* __restrict__ fc3_w, const float* __restrict__ fc3_b,
         const float* __restrict__ fc2_w, const float* __restrict__ fc2_b)
{
    constexpr int K   = IN_W + HID;        // 70 or 128
    constexpr int NKC = (K + 15) / 16;     // k-chunks of 16 (5 or 8)

    extern __shared__ char smem[];
    float* gsp   = (float*)(smem + OFF_GS);
    float* headp = (float*)(smem + OFF_HEAD);

    const int tid = threadIdx.x;
    const int wid = tid >> 5, lid = tid & 31;
    const int b0  = blockIdx.x * B_TILE;

    // ---- fragment identity ----
    const int fg = lid >> 2;               // group row 0..7
    const int fc = lid & 3;                // col group 0..3
    const int m0 = 16 * wid + fg;          // gate rows this thread covers
    const int m1 = m0 + 8;
    const int c4 = 2 * fc;                 // k offset within chunk

    // ---- A fragments (weights) -> registers, hi/lo split, once ----
    // row m (=u*4+gt) maps to original gate-major row r=(m&3)*64+(m>>2)
    uint32_t ahi[NKC][4], alo[NKC][4];
    {
        auto wv = [&](int m, int k) -> float {
            int r = (m & 3) * HID + (m >> 2);
            if (k < IN_W) return w_ih[r * IN_W + k];
            if (k < K)    return w_hh[r * HID + (k - IN_W)];
            return 0.0f;
        };
#pragma unroll
        for (int kc = 0; kc < NKC; kc++) {
            int k0 = 16 * kc + c4;
            float v[8] = { wv(m0, k0),     wv(m0, k0 + 1),
                           wv(m1, k0),     wv(m1, k0 + 1),
                           wv(m0, k0 + 8), wv(m0, k0 + 9),
                           wv(m1, k0 + 8), wv(m1, k0 + 9) };
#pragma unroll
            for (int j = 0; j < 4; j++) {
                float h0f = __bfloat162float(__float2bfloat16(v[2 * j]));
                float h1f = __bfloat162float(__float2bfloat16(v[2 * j + 1]));
                ahi[kc][j] = packbf(v[2 * j], v[2 * j + 1]);
                alo[kc][j] = packbf(v[2 * j] - h0f, v[2 * j + 1] - h1f);
            }
        }
    }

    // B-fragment base pointers: n = fg (batch row), k base = c4
    const uint32_t* bhi_p = (const uint32_t*)(smem + OFF_BHI + fg * XH_STRIDE + c4 * 2);
    const uint32_t* blo_p = (const uint32_t*)(smem + OFF_BLO + fg * XH_STRIDE + c4 * 2);

    // ---- epilogue identity + bias ----
    const int u_e = tid & 63, b_e = tid >> 6;
    float4 bias;
    bias.x = b_ih[0 * HID + u_e] + b_hh[0 * HID + u_e];
    bias.y = b_ih[1 * HID + u_e] + b_hh[1 * HID + u_e];
    bias.z = b_ih[2 * HID + u_e] + b_hh[2 * HID + u_e];
    bias.w = b_ih[3 * HID + u_e] + b_hh[3 * HID + u_e];
    float c_state = 0.0f;

    // ---- init: zero xh tiles (incl. pad cols), then x(0) ----
    for (int i = tid; i < (2 * 2176) / 4; i += NT) ((uint32_t*)smem)[i] = 0u;
    __syncthreads();
    if (IN_W == 64) {
        store_bpair(smem, tid >> 6, tid & 63,
                    x[((size_t)(b0 + (tid >> 6)) * T_STEPS + 0) * IN_W + (tid & 63)]);
    } else if (tid < IN_W * B_TILE) {
        int b = tid / IN_W, k = tid - b * IN_W;
        store_bpair(smem, b, k, x[((size_t)(b0 + b) * T_STEPS + 0) * IN_W + k]);
    }
    __syncthreads();

    for (int t = 0; t < T_STEPS; t++) {
        // prefetch x(t+1)
        float xpre = 0.f; int pb = 0, pk = 0;
        if (t + 1 < T_STEPS) {
            if (IN_W == 64) {
                pb = tid >> 6; pk = tid & 63;
                xpre = x[((size_t)(b0 + pb) * T_STEPS + (t + 1)) * IN_W + pk];
            } else if (tid < IN_W * B_TILE) {
                pb = tid / IN_W; pk = tid - pb * IN_W;
                xpre = x[((size_t)(b0 + pb) * T_STEPS + (t + 1)) * IN_W + pk];
            }
        }

        // ---- GEMM: bf16x3 passes, fp32 accum ----
        float d[4] = {0.f, 0.f, 0.f, 0.f};
#pragma unroll
        for (int kc = 0; kc < NKC; kc++) {
            uint32_t bh0 = bhi_p[8 * kc], bh1 = bhi_p[8 * kc + 4];
            uint32_t bl0 = blo_p[8 * kc], bl1 = blo_p[8 * kc + 4];
            mma16816(d, ahi[kc], bh0, bh1);   // hi * hi
            mma16816(d, ahi[kc], bl0, bl1);   // hi * lo
            mma16816(d, alo[kc], bh0, bh1);   // lo * hi
        }
        // ---- stage: gs[batch][row] (conflict-free STS.32) ----
        gsp[(c4 + 0) * GS_STRIDE + m0] = d[0];
        gsp[(c4 + 1) * GS_STRIDE + m0] = d[1];
        gsp[(c4 + 0) * GS_STRIDE + m1] = d[2];
        gsp[(c4 + 1) * GS_STRIDE + m1] = d[3];
        __syncthreads();   // gates staged; xh reads for step t done

        // ---- epilogue for (u_e, b_e): rows 4u..4u+3 = (i,f,g,o) ----
        {
            float4 g = *(const float4*)(gsp + b_e * GS_STRIDE + 4 * u_e);
            float gi = g.x + bias.x, gf = g.y + bias.y;
            float gg = g.z + bias.z, go = g.w + bias.w;
            float iv = sigf(gi), fv = sigf(gf), gv = tanh_fast(gg), ov = sigf(go);
            c_state = fv * c_state + iv * gv;
            float h = ov * tanh_fast(c_state);

            store_bpair(smem, b_e, IN_W + u_e, h);

            if (!LAST) {
                y[((size_t)(b0 + b_e) * T_STEPS + t) * HID + u_e] = h;
            } else if (t == T_STEPS - 1) {
                headp[b_e * HID + u_e] = h;
            }
        }
        // x(t+1) into xh
        if (t + 1 < T_STEPS) {
            if (IN_W == 64)                 store_bpair(smem, pb, pk, xpre);
            else if (tid < IN_W * B_TILE)   store_bpair(smem, pb, pk, xpre);
        }
        __syncthreads();   // xh(t+1) + gs reuse ready
    }

    // ---- fused MLP head (LAST only) ----
    if (LAST) {
        float* h_s = headp;            // [8][64]
        float* z1  = headp + 512;      // [8][128]
        float* z2  = headp + 1536;     // [8][64]
        __syncthreads();
        for (int v = tid; v < 8 * 128; v += NT) {
            int b = v >> 7, j = v & 127;
            float s = fc1_b[j];
#pragma unroll 8
            for (int k = 0; k < 64; k++) s += h_s[b * 64 + k] * fc1_w[j * 64 + k];
            z1[b * 128 + j] = fmaxf(s, 0.0f);
        }
        __syncthreads();
        for (int v = tid; v < 8 * 64; v += NT) {
            int b = v >> 6, j = v & 63;
            float s = fc3_b[j];
#pragma unroll 8
            for (int k = 0; k < 128; k++) s += z1[b * 128 + k] * fc3_w[j * 128 + k];
            z2[b * 64 + j] = fmaxf(s, 0.0f);
        }
        __syncthreads();
        if (tid < 16) {
            int b = tid >> 1, j = tid & 1;
            float s = fc2_b[j];
#pragma unroll
            for (int k = 0; k < 64; k++) s += z2[b * 64 + k] * fc2_w[j * 64 + k];
            y[(b0 + b) * 2 + j] = s;
        }
    }
}

extern "C" void kernel_launch(void* const* d_in, const int* in_sizes, int n_in,
                              void* d_out, int out_size)
{
    const float* x     = (const float*)d_in[0];
    const float* w_ih0 = (const float*)d_in[1];
    const float* w_hh0 = (const float*)d_in[2];
    const float* b_ih0 = (const float*)d_in[3];
    const float* b_hh0 = (const float*)d_in[4];
    const float* w_ih1 = (const float*)d_in[5];
    const float* w_hh1 = (const float*)d_in[6];
    const float* b_ih1 = (const float*)d_in[7];
    const float* b_hh1 = (const float*)d_in[8];
    const float* w_ih2 = (const float*)d_in[9];
    const float* w_hh2 = (const float*)d_in[10];
    const float* b_ih2 = (const float*)d_in[11];
    const float* b_hh2 = (const float*)d_in[12];
    const float* fc1_w = (const float*)d_in[13];
    const float* fc1_b = (const float*)d_in[14];
    const float* fc3_w = (const float*)d_in[15];
    const float* fc3_b = (const float*)d_in[16];
    const float* fc2_w = (const float*)d_in[17];
    const float* fc2_b = (const float*)d_in[18];
    float* out = (float*)d_out;

    float *buf0 = nullptr, *buf1 = nullptr;
    cudaGetSymbolAddress((void**)&buf0, g_buf0);
    cudaGetSymbolAddress((void**)&buf1, g_buf1);

    const int GRID = BATCH / B_TILE;   // 128

    lstm_mma<6,  false><<<GRID, NT, SM_TOTAL>>>(x,    w_ih0, w_hh0, b_ih0, b_hh0, buf0,
                                                nullptr, nullptr, nullptr, nullptr, nullptr, nullptr);
    lstm_mma<64, false><<<GRID, NT, SM_TOTAL>>>(buf0, w_ih1, w_hh1, b_ih1, b_hh1, buf1,
                                                nullptr, nullptr, nullptr, nullptr, nullptr, nullptr);
    lstm_mma<64, true ><<<GRID, NT, SM_TOTAL>>>(buf1, w_ih2, w_hh2, b_ih2, b_hh2, out,
                                                fc1_w, fc1_b, fc3_w, fc3_b, fc2_w, fc2_b);
}